// round 3
// baseline (speedup 1.0000x reference)
#include <cuda_runtime.h>
#include <cstdint>

#define NQ 16
#define NL 8
#define BATCH 512
#define DIM 65536
#define BT 32
#define BCHUNK 128
#define NCHUNK (BATCH / BCHUNK)

// 256 MB state scratch, layout [slot p][batch] (batch contiguous -> coalesced)
__device__ float2 g_state[(size_t)DIM * BATCH];
// partial reduction scratch [slotblock 0..127][batch][wire]
__device__ float g_part[(size_t)128 * BATCH * NQ];

struct PassArgs {
    unsigned short mask[8];     // Licol of the 8 wires (pair masks)
    unsigned short selrow[8];   // Lrow of the 8 wires (selector rows)
    unsigned char  freepos[8];  // bit positions for coset representative
    int layer, gbase, b0;
};
struct MeasArgs {
    unsigned short fsel[16];    // final Lrow per wire
    int b0;
};

// ---------------------------------------------------------------------------
// Init: product state. amp(p) = prod_i (bit_i(p) ? sin(pi x_i/2) : cos(...))
// grid (DIM/256, BCHUNK/BT), 256 threads
// ---------------------------------------------------------------------------
__global__ __launch_bounds__(256) void qsim_init(const float* __restrict__ x, int b0) {
    __shared__ float c0[NQ][BT];
    __shared__ float s0[NQ][BT];
    int tid = threadIdx.x;
    int bbase = b0 + blockIdx.y * BT;
    for (int idx = tid; idx < NQ * BT; idx += 256) {
        int b = idx & 31, i = idx >> 5;
        float xv = x[(bbase + b) * NQ + i];
        float s, c;
        sincospif(0.5f * xv, &s, &c);
        c0[i][b] = c;
        s0[i][b] = s;
    }
    __syncthreads();
    int b = tid & 31, pl = tid >> 5;
    int pbase = blockIdx.x * 256;
    for (int e = 0; e < 32; e++) {
        int p = pbase + pl + e * 8;
        float amp = 1.0f;
#pragma unroll
        for (int i = 0; i < NQ; i++)
            amp *= ((p >> i) & 1) ? s0[i][b] : c0[i][b];
        g_state[(size_t)p * BATCH + bbase + b] = make_float2(amp, 0.0f);
    }
}

// ---------------------------------------------------------------------------
// Pass: 8 Rot gates (half a layer) on a 256-coset x 32-batch tile.
// grid (256 cosets, BCHUNK/BT), 256 threads, 66560 B dynamic smem
// ---------------------------------------------------------------------------
__global__ __launch_bounds__(256) void qsim_pass(const float* __restrict__ wts, PassArgs pa) {
    extern __shared__ char smraw[];
    float2* S = (float2*)smraw;                                   // 64 KB tile
    unsigned short* offt = (unsigned short*)(smraw + 65536);      // 512 B
    float2* G = (float2*)(smraw + 66048);                         // 8 gates x 4

    int tid = threadIdx.x;
    unsigned cid = blockIdx.x;
    unsigned rep = 0;
#pragma unroll
    for (int k = 0; k < 8; k++)
        if ((cid >> k) & 1) rep |= (1u << pa.freepos[k]);

    // offset table: offt[t] = XOR of masks selected by bits of t
    {
        unsigned v = 0;
#pragma unroll
        for (int k = 0; k < 8; k++)
            if ((tid >> k) & 1) v ^= pa.mask[k];
        offt[tid] = (unsigned short)v;
    }

    // gate matrices, pre-swapped by the CTA-uniform selector parity
    if (tid < 8) {
        const float* wp = wts + ((size_t)pa.layer * NQ + pa.gbase + tid) * 3;
        float phi = wp[0], th = wp[1], om = wp[2];
        float c, s, ca, sa, cb, sb;
        sincosf(0.5f * th, &s, &c);
        sincosf(0.5f * (phi + om), &sa, &ca);
        sincosf(0.5f * (phi - om), &sb, &cb);
        float2 u00 = make_float2(c * ca, -c * sa);
        float2 u01 = make_float2(-s * cb, -s * sb);
        float2 u10 = make_float2(s * cb, -s * sb);
        float2 u11 = make_float2(c * ca, c * sa);
        int fl = __popc((unsigned)pa.selrow[tid] & rep) & 1;
        float2* g = G + tid * 4;
        if (!fl) { g[0] = u00; g[1] = u01; g[2] = u10; g[3] = u11; }
        else     { g[0] = u11; g[1] = u10; g[2] = u01; g[3] = u00; }
    }
    __syncthreads();

    int b = tid & 31, tr = tid >> 5;
    int bbase = pa.b0 + blockIdx.y * BT;

    // load tile (warp reads one t-row of 32 batch = 256B contiguous)
#pragma unroll 4
    for (int e = 0; e < 32; e++) {
        int t = tr + e * 8;
        unsigned p = rep ^ (unsigned)offt[t];
        S[t * 32 + b] = g_state[(size_t)p * BATCH + bbase + b];
    }
    __syncthreads();

    float2 v[16];

    // Round A: gates 0..3 act on bits 0..3 of t (register-resident 16-cube)
#pragma unroll
    for (int sub = 0; sub < 2; sub++) {
        int thi = tr + 8 * sub;
        float2* base = S + thi * 512 + b;
#pragma unroll
        for (int j = 0; j < 16; j++) v[j] = base[j * 32];
#pragma unroll
        for (int g = 0; g < 4; g++) {
            float2 g00 = G[g * 4 + 0], g01 = G[g * 4 + 1];
            float2 g10 = G[g * 4 + 2], g11 = G[g * 4 + 3];
#pragma unroll
            for (int j = 0; j < 16; j++) {
                if (j & (1 << g)) continue;
                int j1 = j | (1 << g);
                float2 a0 = v[j], a1 = v[j1];
                float2 r0, r1;
                r0.x = g00.x * a0.x - g00.y * a0.y + g01.x * a1.x - g01.y * a1.y;
                r0.y = g00.x * a0.y + g00.y * a0.x + g01.x * a1.y + g01.y * a1.x;
                r1.x = g10.x * a0.x - g10.y * a0.y + g11.x * a1.x - g11.y * a1.y;
                r1.y = g10.x * a0.y + g10.y * a0.x + g11.x * a1.y + g11.y * a1.x;
                v[j] = r0; v[j1] = r1;
            }
        }
#pragma unroll
        for (int j = 0; j < 16; j++) base[j * 32] = v[j];
    }
    __syncthreads();

    // Round B: gates 4..7 act on bits 4..7 of t
#pragma unroll
    for (int sub = 0; sub < 2; sub++) {
        int tlo = tr + 8 * sub;
        float2* base = S + tlo * 32 + b;
#pragma unroll
        for (int j = 0; j < 16; j++) v[j] = base[j * 512];
#pragma unroll
        for (int g = 0; g < 4; g++) {
            float2 g00 = G[(g + 4) * 4 + 0], g01 = G[(g + 4) * 4 + 1];
            float2 g10 = G[(g + 4) * 4 + 2], g11 = G[(g + 4) * 4 + 3];
#pragma unroll
            for (int j = 0; j < 16; j++) {
                if (j & (1 << g)) continue;
                int j1 = j | (1 << g);
                float2 a0 = v[j], a1 = v[j1];
                float2 r0, r1;
                r0.x = g00.x * a0.x - g00.y * a0.y + g01.x * a1.x - g01.y * a1.y;
                r0.y = g00.x * a0.y + g00.y * a0.x + g01.x * a1.y + g01.y * a1.x;
                r1.x = g10.x * a0.x - g10.y * a0.y + g11.x * a1.x - g11.y * a1.y;
                r1.y = g10.x * a0.y + g10.y * a0.x + g11.x * a1.y + g11.y * a1.x;
                v[j] = r0; v[j1] = r1;
            }
        }
#pragma unroll
        for (int j = 0; j < 16; j++) base[j * 512] = v[j];
    }
    __syncthreads();

    // store tile
#pragma unroll 4
    for (int e = 0; e < 32; e++) {
        int t = tr + e * 8;
        unsigned p = rep ^ (unsigned)offt[t];
        g_state[(size_t)p * BATCH + bbase + b] = S[t * 32 + b];
    }
}

// ---------------------------------------------------------------------------
// Measure: per (slotblock, batch-tile), sign-weighted |amp|^2 partial sums.
// grid (128, BCHUNK/BT), 256 threads
// ---------------------------------------------------------------------------
__global__ __launch_bounds__(256) void qsim_measure(MeasArgs ma) {
    __shared__ float red[8 * 32 * 16];  // 16 KB
    int tid = threadIdx.x;
    int b = tid & 31, sl = tid >> 5;
    int bbase = ma.b0 + blockIdx.y * BT;
    int pbase = blockIdx.x * 512;
    float acc[16];
#pragma unroll
    for (int i = 0; i < 16; i++) acc[i] = 0.0f;
    for (int e = 0; e < 64; e++) {
        int p = pbase + sl + e * 8;
        float2 a = g_state[(size_t)p * BATCH + bbase + b];
        float w = a.x * a.x + a.y * a.y;
#pragma unroll
        for (int i = 0; i < 16; i++)
            acc[i] += (__popc((unsigned)ma.fsel[i] & (unsigned)p) & 1) ? -w : w;
    }
#pragma unroll
    for (int i = 0; i < 16; i++) red[(sl * 32 + b) * 16 + i] = acc[i];
    __syncthreads();
#pragma unroll
    for (int r = 0; r < 2; r++) {
        int pr = tid + r * 256;           // (b,i) pair index, 512 total
        int bb = pr >> 4, ii = pr & 15;
        float s = 0.0f;
#pragma unroll
        for (int s2 = 0; s2 < 8; s2++) s += red[(s2 * 32 + bb) * 16 + ii];
        g_part[(size_t)blockIdx.x * (BATCH * NQ) + (size_t)(bbase + bb) * NQ + ii] = s;
    }
}

// Final deterministic reduction over 128 slotblocks -> out[b*16+i]
__global__ __launch_bounds__(256) void qsim_final(float* __restrict__ out) {
    int v = blockIdx.x * 256 + threadIdx.x;  // 0..8191
    float s = 0.0f;
    for (int sb = 0; sb < 128; sb++) s += g_part[(size_t)sb * (BATCH * NQ) + v];
    out[v] = s;
}

// ---------------------------------------------------------------------------
extern "C" void kernel_launch(void* const* d_in, const int* in_sizes, int n_in,
                              void* d_out, int out_size) {
    const float* x = (const float*)d_in[0];
    const float* w = (const float*)d_in[1];
    float* out = (float*)d_out;

    // Host-side GF(2) tracking of the CNOT network.
    // A[p] = psi[L p]; Lrow = rows of L, Licol = columns of L^{-1}.
    unsigned short Lrow[NQ], Licol[NQ];
    for (int i = 0; i < NQ; i++) { Lrow[i] = (unsigned short)(1u << i); Licol[i] = (unsigned short)(1u << i); }

    PassArgs pa[NL][2];
    for (int l = 0; l < NL; l++) {
        for (int half = 0; half < 2; half++) {
            PassArgs& a = pa[l][half];
            a.layer = l; a.gbase = half * 8; a.b0 = 0;
            for (int k = 0; k < 8; k++) {
                a.mask[k] = Licol[half * 8 + k];
                a.selrow[k] = Lrow[half * 8 + k];
            }
            // RREF over the 8 masks -> pivot bits; free bits index coset reps
            unsigned short red[8]; int piv[8]; unsigned pivmask = 0;
            for (int k = 0; k < 8; k++) {
                unsigned short vv = a.mask[k];
                for (int j = 0; j < k; j++)
                    if ((vv >> piv[j]) & 1) vv ^= red[j];
                int p = 0;
                while (!((vv >> p) & 1)) p++;
                piv[k] = p; red[k] = vv; pivmask |= (1u << p);
                for (int j = 0; j < k; j++)
                    if ((red[j] >> p) & 1) red[j] ^= vv;
            }
            int f = 0;
            for (int bit = 0; bit < NQ; bit++)
                if (!((pivmask >> bit) & 1)) a.freepos[f++] = (unsigned char)bit;
        }
        // apply CNOT ring: L <- C L (row op), L^{-1} <- L^{-1} C (col op)
        int r = l % (NQ - 1) + 1;
        for (int i = 0; i < NQ; i++) {
            int c = i, t = (i + r) % NQ;
            Lrow[t] = (unsigned short)(Lrow[t] ^ Lrow[c]);
            Licol[c] = (unsigned short)(Licol[c] ^ Licol[t]);
        }
    }
    MeasArgs ma;
    for (int i = 0; i < NQ; i++) ma.fsel[i] = Lrow[i];

    const int SM_PASS = 66560;
    cudaFuncSetAttribute(qsim_pass, cudaFuncAttributeMaxDynamicSharedMemorySize, SM_PASS);

    for (int c = 0; c < NCHUNK; c++) {
        int b0 = c * BCHUNK;
        qsim_init<<<dim3(DIM / 256, BCHUNK / BT), 256>>>(x, b0);
        for (int l = 0; l < NL; l++)
            for (int half = 0; half < 2; half++) {
                PassArgs a = pa[l][half];
                a.b0 = b0;
                qsim_pass<<<dim3(256, BCHUNK / BT), 256, SM_PASS>>>(w, a);
            }
        MeasArgs m2 = ma;
        m2.b0 = b0;
        qsim_measure<<<dim3(128, BCHUNK / BT), 256>>>(m2);
    }
    qsim_final<<<32, 256>>>(out);
}

// round 4
// speedup vs baseline: 1.5276x; 1.5276x over previous
#include <cuda_runtime.h>
#include <cstdint>

#define NQ 16
#define NL 8
#define BATCH 512
#define DIM 65536
#define BCHUNK 128
#define NCHUNK (BATCH / BCHUNK)
#define TB 16               // batches per tile
#define TT 256              // t-slots per tile
#define NBT (BCHUNK / TB)   // 8 batch tiles per chunk

typedef unsigned long long ull;

// 256 MB state scratch, packed complex (lo=re, hi=im), layout [slot][batch]
__device__ ull g_state[(size_t)DIM * BATCH];
// partial reduction scratch [slotblock 0..127][batch][wire]
__device__ float g_part[(size_t)128 * BATCH * NQ];

struct PassArgs {
    unsigned short mask[8];     // Licol of the 8 wires (pair masks)
    unsigned short selrow[8];   // Lrow of the 8 wires (selector rows)
    unsigned char  freepos[8];  // bit positions for coset representative
    int layer, gbase, b0, first;
};
struct MeasArgs {
    unsigned short fsel[16];
    int b0;
};

// ---- packed f32x2 helpers (Blackwell) -------------------------------------
__device__ __forceinline__ ull ffma2(ull a, ull b, ull c) {
    ull d;
    asm("fma.rn.f32x2 %0, %1, %2, %3;" : "=l"(d) : "l"(a), "l"(b), "l"(c));
    return d;
}
__device__ __forceinline__ ull fmul2(ull a, ull b) {
    ull d;
    asm("mul.rn.f32x2 %0, %1, %2;" : "=l"(d) : "l"(a), "l"(b));
    return d;
}
__device__ __forceinline__ ull swap2(ull a) {
    ull d;
    asm("{\n\t.reg .b32 lo, hi;\n\tmov.b64 {lo, hi}, %1;\n\tmov.b64 %0, {hi, lo};\n\t}"
        : "=l"(d) : "l"(a));
    return d;
}
__device__ __forceinline__ ull pack2(float lo, float hi) {
    ull d;
    asm("mov.b64 %0, {%1, %2};" : "=l"(d) : "f"(lo), "f"(hi));
    return d;
}

// ---------------------------------------------------------------------------
// Pass: 8 Rot gates (half a layer) on a 256-coset x 16-batch tile.
// grid (256 cosets, NBT), 256 threads. first==1: synthesize product state.
// ---------------------------------------------------------------------------
__global__ __launch_bounds__(256, 3) void qsim_pass(const float* __restrict__ x,
                                                    const float* __restrict__ wts,
                                                    PassArgs pa) {
    __shared__ __align__(16) ull S[TT * TB];       // 32 KB tile
    __shared__ unsigned short offt[256];
    __shared__ ull Gp[64];                         // 8 gates x 8 packed consts
    __shared__ float2 cst[NQ * TB];                // (cos, sin) per (wire, b)

    int tid = threadIdx.x;
    unsigned rep = 0;
#pragma unroll
    for (int k = 0; k < 8; k++)
        if ((blockIdx.x >> k) & 1) rep |= (1u << pa.freepos[k]);

    // offset table: offt[t] = XOR of masks selected by bits of t
    {
        unsigned v = 0;
#pragma unroll
        for (int k = 0; k < 8; k++)
            if ((tid >> k) & 1) v ^= pa.mask[k];
        offt[tid] = (unsigned short)v;
    }

    int bbase = pa.b0 + blockIdx.y * TB;

    if (pa.first) {
        int i = tid >> 4, b = tid & 15;
        float s, c;
        sincospif(0.5f * x[(bbase + b) * NQ + i], &s, &c);
        cst[i * TB + b] = make_float2(c, s);
    }

    // gate matrices, pre-swapped by the CTA-uniform selector parity, packed:
    // per coefficient u: A=(u.re,u.re), B=(-u.im,u.im)
    if (tid < 8) {
        const float* wp = wts + ((size_t)pa.layer * NQ + pa.gbase + tid) * 3;
        float phi = wp[0], th = wp[1], om = wp[2];
        float c, s, ca, sa, cb, sb;
        sincosf(0.5f * th, &s, &c);
        sincosf(0.5f * (phi + om), &sa, &ca);
        sincosf(0.5f * (phi - om), &sb, &cb);
        float2 u00 = make_float2(c * ca, -c * sa);
        float2 u01 = make_float2(-s * cb, -s * sb);
        float2 u10 = make_float2(s * cb, -s * sb);
        float2 u11 = make_float2(c * ca, c * sa);
        int fl = __popc((unsigned)pa.selrow[tid] & rep) & 1;
        float2 m00 = fl ? u11 : u00, m01 = fl ? u10 : u01;
        float2 m10 = fl ? u01 : u10, m11 = fl ? u00 : u11;
        ull* g = Gp + tid * 8;
        g[0] = pack2(m00.x, m00.x); g[1] = pack2(-m00.y, m00.y);
        g[2] = pack2(m01.x, m01.x); g[3] = pack2(-m01.y, m01.y);
        g[4] = pack2(m10.x, m10.x); g[5] = pack2(-m10.y, m10.y);
        g[6] = pack2(m11.x, m11.x); g[7] = pack2(-m11.y, m11.y);
    }
    __syncthreads();

    int bp = tid & 7, trow = tid >> 3;   // load/store mapping: 2 batches/thread

    if (!pa.first) {
        unsigned sbase = (unsigned)__cvta_generic_to_shared(S);
#pragma unroll
        for (int e = 0; e < 8; e++) {
            int t = trow + 32 * e;
            unsigned p = rep ^ (unsigned)offt[t];
            const ull* src = &g_state[(size_t)p * BATCH + bbase + 2 * bp];
            unsigned dst = sbase + (unsigned)(t * TB + 2 * bp) * 8u;
            asm volatile("cp.async.cg.shared.global [%0], [%1], 16;"
                         :: "r"(dst), "l"(src));
        }
        asm volatile("cp.async.commit_group;");
        asm volatile("cp.async.wait_group 0;");
    } else {
        // synthesize product state: amp(p,b) = prod_i (bit_i(p) ? sin : cos)
#pragma unroll
        for (int e = 0; e < 8; e++) {
            int t = trow + 32 * e;
            unsigned p = rep ^ (unsigned)offt[t];
            float a0 = 1.0f, a1 = 1.0f;
#pragma unroll
            for (int i = 0; i < NQ; i++) {
                float2 c0 = cst[i * TB + 2 * bp];
                float2 c1 = cst[i * TB + 2 * bp + 1];
                int bit = (p >> i) & 1;
                a0 *= bit ? c0.y : c0.x;
                a1 *= bit ? c1.y : c1.x;
            }
            S[t * TB + 2 * bp]     = pack2(a0, 0.0f);
            S[t * TB + 2 * bp + 1] = pack2(a1, 0.0f);
        }
    }
    __syncthreads();

    int b = tid & 15, thi = tid >> 4;    // round mapping: 1 batch/thread, 16-cube

    // Round A: gates 0..3 act on t bits 0..3 (j), t = thi*16 + j
    {
        int base = thi * 256 + b;
        ull v[16];
#pragma unroll
        for (int j = 0; j < 16; j++) v[j] = S[base + j * 16];
#pragma unroll
        for (int g = 0; g < 4; g++) {
            ull gc[8];
#pragma unroll
            for (int k = 0; k < 8; k++) gc[k] = Gp[g * 8 + k];
#pragma unroll
            for (int j = 0; j < 16; j++) {
                if (j & (1 << g)) continue;
                int j1 = j | (1 << g);
                ull a0 = v[j], a1 = v[j1];
                ull a0s = swap2(a0), a1s = swap2(a1);
                v[j]  = ffma2(gc[0], a0, ffma2(gc[1], a0s, ffma2(gc[2], a1, fmul2(gc[3], a1s))));
                v[j1] = ffma2(gc[4], a0, ffma2(gc[5], a0s, ffma2(gc[6], a1, fmul2(gc[7], a1s))));
            }
        }
#pragma unroll
        for (int j = 0; j < 16; j++) S[base + j * 16] = v[j];
    }
    __syncthreads();

    // Round B: gates 4..7 act on t bits 4..7 (j), t = j*16 + tlo
    {
        int base = thi * 16 + b;
        ull v[16];
#pragma unroll
        for (int j = 0; j < 16; j++) v[j] = S[base + j * 256];
#pragma unroll
        for (int g = 0; g < 4; g++) {
            ull gc[8];
#pragma unroll
            for (int k = 0; k < 8; k++) gc[k] = Gp[(g + 4) * 8 + k];
#pragma unroll
            for (int j = 0; j < 16; j++) {
                if (j & (1 << g)) continue;
                int j1 = j | (1 << g);
                ull a0 = v[j], a1 = v[j1];
                ull a0s = swap2(a0), a1s = swap2(a1);
                v[j]  = ffma2(gc[0], a0, ffma2(gc[1], a0s, ffma2(gc[2], a1, fmul2(gc[3], a1s))));
                v[j1] = ffma2(gc[4], a0, ffma2(gc[5], a0s, ffma2(gc[6], a1, fmul2(gc[7], a1s))));
            }
        }
#pragma unroll
        for (int j = 0; j < 16; j++) S[base + j * 256] = v[j];
    }
    __syncthreads();

    // store tile (128-bit)
#pragma unroll
    for (int e = 0; e < 8; e++) {
        int t = trow + 32 * e;
        unsigned p = rep ^ (unsigned)offt[t];
        ulonglong2 w = *(const ulonglong2*)&S[t * TB + 2 * bp];
        *(ulonglong2*)&g_state[(size_t)p * BATCH + bbase + 2 * bp] = w;
    }
}

// ---------------------------------------------------------------------------
// Measure: per (slotblock, 32-batch tile), sign-weighted |amp|^2 partials.
// grid (128, BCHUNK/32), 256 threads
// ---------------------------------------------------------------------------
__global__ __launch_bounds__(256) void qsim_measure(MeasArgs ma) {
    __shared__ float red[8 * 32 * 16];
    const float2* st = (const float2*)g_state;
    int tid = threadIdx.x;
    int b = tid & 31, sl = tid >> 5;
    int bbase = ma.b0 + blockIdx.y * 32;
    int pbase = blockIdx.x * 512;
    float acc[16];
#pragma unroll
    for (int i = 0; i < 16; i++) acc[i] = 0.0f;
    for (int e = 0; e < 64; e++) {
        int p = pbase + sl + e * 8;
        float2 a = st[(size_t)p * BATCH + bbase + b];
        float w = a.x * a.x + a.y * a.y;
#pragma unroll
        for (int i = 0; i < 16; i++)
            acc[i] += (__popc((unsigned)ma.fsel[i] & (unsigned)p) & 1) ? -w : w;
    }
#pragma unroll
    for (int i = 0; i < 16; i++) red[(sl * 32 + b) * 16 + i] = acc[i];
    __syncthreads();
#pragma unroll
    for (int r = 0; r < 2; r++) {
        int pr = tid + r * 256;
        int bb = pr >> 4, ii = pr & 15;
        float s = 0.0f;
#pragma unroll
        for (int s2 = 0; s2 < 8; s2++) s += red[(s2 * 32 + bb) * 16 + ii];
        g_part[(size_t)blockIdx.x * (BATCH * NQ) + (size_t)(bbase + bb) * NQ + ii] = s;
    }
}

__global__ __launch_bounds__(256) void qsim_final(float* __restrict__ out) {
    int v = blockIdx.x * 256 + threadIdx.x;
    float s = 0.0f;
    for (int sb = 0; sb < 128; sb++) s += g_part[(size_t)sb * (BATCH * NQ) + v];
    out[v] = s;
}

// ---------------------------------------------------------------------------
extern "C" void kernel_launch(void* const* d_in, const int* in_sizes, int n_in,
                              void* d_out, int out_size) {
    const float* x = (const float*)d_in[0];
    const float* w = (const float*)d_in[1];
    float* out = (float*)d_out;

    // Host-side GF(2) tracking of the CNOT network.
    unsigned short Lrow[NQ], Licol[NQ];
    for (int i = 0; i < NQ; i++) { Lrow[i] = (unsigned short)(1u << i); Licol[i] = (unsigned short)(1u << i); }

    PassArgs pa[NL][2];
    for (int l = 0; l < NL; l++) {
        for (int half = 0; half < 2; half++) {
            PassArgs& a = pa[l][half];
            a.layer = l; a.gbase = half * 8; a.b0 = 0; a.first = 0;
            for (int k = 0; k < 8; k++) {
                a.mask[k] = Licol[half * 8 + k];
                a.selrow[k] = Lrow[half * 8 + k];
            }
            unsigned short red[8]; int piv[8]; unsigned pivmask = 0;
            for (int k = 0; k < 8; k++) {
                unsigned short vv = a.mask[k];
                for (int j = 0; j < k; j++)
                    if ((vv >> piv[j]) & 1) vv ^= red[j];
                int p = 0;
                while (!((vv >> p) & 1)) p++;
                piv[k] = p; red[k] = vv; pivmask |= (1u << p);
                for (int j = 0; j < k; j++)
                    if ((red[j] >> p) & 1) red[j] ^= vv;
            }
            int f = 0;
            for (int bit = 0; bit < NQ; bit++)
                if (!((pivmask >> bit) & 1)) a.freepos[f++] = (unsigned char)bit;
        }
        int r = l % (NQ - 1) + 1;
        for (int i = 0; i < NQ; i++) {
            int c = i, t = (i + r) % NQ;
            Lrow[t] = (unsigned short)(Lrow[t] ^ Lrow[c]);
            Licol[c] = (unsigned short)(Licol[c] ^ Licol[t]);
        }
    }
    MeasArgs ma;
    for (int i = 0; i < NQ; i++) ma.fsel[i] = Lrow[i];

    for (int c = 0; c < NCHUNK; c++) {
        int b0 = c * BCHUNK;
        for (int l = 0; l < NL; l++)
            for (int half = 0; half < 2; half++) {
                PassArgs a = pa[l][half];
                a.b0 = b0;
                a.first = (l == 0 && half == 0) ? 1 : 0;
                qsim_pass<<<dim3(256, NBT), 256>>>(x, w, a);
            }
        MeasArgs m2 = ma;
        m2.b0 = b0;
        qsim_measure<<<dim3(128, BCHUNK / 32), 256>>>(m2);
    }
    qsim_final<<<32, 256>>>(out);
}

// round 5
// speedup vs baseline: 1.8538x; 1.2136x over previous
#include <cuda_runtime.h>
#include <cstdint>

#define NQ 16
#define NL 8
#define BATCH 512
#define DIM 65536
#define BCHUNK 128
#define NCHUNK (BATCH / BCHUNK)
#define TB 16
#define NBT (BCHUNK / TB)

typedef unsigned long long ull;

// 256 MB state, packed complex (lo=re, hi=im), layout [slot][batch]
__device__ ull g_state[(size_t)DIM * BATCH];
// measurement partials [coset 0..255][batch][wire]
__device__ float g_part[(size_t)256 * BATCH * NQ];

struct PassArgs {
    unsigned short mask[8];     // Licol of the 8 wires (pair masks)
    unsigned short selrow[8];   // Lrow of the 8 wires (selector rows)
    unsigned char  freepos[8];  // coset representative bit positions
    unsigned short sm0[4];      // sign-words of masks 0-3 (last pass)
    unsigned short sm4[4];      // sign-words of masks 4-7 (last pass)
    unsigned short sfb[8];      // sign-words of freepos bits (last pass)
    int layer, gbase, b0, first, last;
};

// ---- packed f32x2 helpers (Blackwell) -------------------------------------
__device__ __forceinline__ ull ffma2(ull a, ull b, ull c) {
    ull d;
    asm("fma.rn.f32x2 %0, %1, %2, %3;" : "=l"(d) : "l"(a), "l"(b), "l"(c));
    return d;
}
__device__ __forceinline__ ull fmul2(ull a, ull b) {
    ull d;
    asm("mul.rn.f32x2 %0, %1, %2;" : "=l"(d) : "l"(a), "l"(b));
    return d;
}
__device__ __forceinline__ ull swap2(ull a) {
    ull d;
    asm("{\n\t.reg .b32 lo, hi;\n\tmov.b64 {lo, hi}, %1;\n\tmov.b64 %0, {hi, lo};\n\t}"
        : "=l"(d) : "l"(a));
    return d;
}
__device__ __forceinline__ ull pack2(float lo, float hi) {
    ull d;
    asm("mov.b64 %0, {%1, %2};" : "=l"(d) : "f"(lo), "f"(hi));
    return d;
}
__device__ __forceinline__ float2 unpk(ull a) {
    float2 f;
    asm("mov.b64 {%0, %1}, %2;" : "=f"(f.x), "=f"(f.y) : "l"(a));
    return f;
}

__device__ __forceinline__ unsigned mx4(const unsigned short* m, unsigned s) {
    unsigned r = 0;
    if (s & 1) r ^= m[0];
    if (s & 2) r ^= m[1];
    if (s & 4) r ^= m[2];
    if (s & 8) r ^= m[3];
    return r;
}

// 16-entry XOR tree from 4 masks
__device__ __forceinline__ void xtree(unsigned* p, unsigned base,
                                      unsigned m0, unsigned m1,
                                      unsigned m2, unsigned m3) {
    p[0] = base;
    p[1] = p[0] ^ m0;  p[2] = p[0] ^ m1;  p[3] = p[1] ^ m1;
    p[4] = p[0] ^ m2;  p[5] = p[1] ^ m2;  p[6] = p[2] ^ m2;  p[7] = p[3] ^ m2;
    p[8] = p[0] ^ m3;  p[9] = p[1] ^ m3;  p[10] = p[2] ^ m3; p[11] = p[3] ^ m3;
    p[12] = p[4] ^ m3; p[13] = p[5] ^ m3; p[14] = p[6] ^ m3; p[15] = p[7] ^ m3;
}

__device__ __forceinline__ void bfly4(ull* v, const ull* Gp, int gofs) {
#pragma unroll
    for (int g = 0; g < 4; g++) {
        ull gc[8];
#pragma unroll
        for (int k = 0; k < 8; k++) gc[k] = Gp[(gofs + g) * 8 + k];
#pragma unroll
        for (int j = 0; j < 16; j++) {
            if (j & (1 << g)) continue;
            int j1 = j | (1 << g);
            ull a0 = v[j], a1 = v[j1];
            ull a0s = swap2(a0), a1s = swap2(a1);
            v[j]  = ffma2(gc[0], a0, ffma2(gc[1], a0s, ffma2(gc[2], a1, fmul2(gc[3], a1s))));
            v[j1] = ffma2(gc[4], a0, ffma2(gc[5], a0s, ffma2(gc[6], a1, fmul2(gc[7], a1s))));
        }
    }
}

// ---------------------------------------------------------------------------
// Pass: 8 Rot gates (half a layer) on a 256-coset x 16-batch tile.
// grid (256 cosets, NBT), 256 threads. first: synthesize product state.
// last: fuse <Z_i> measurement, skip state writeback.
// ---------------------------------------------------------------------------
__global__ __launch_bounds__(256, 3) void qsim_pass(const float* __restrict__ x,
                                                    const float* __restrict__ wts,
                                                    PassArgs pa) {
    __shared__ __align__(16) ull S[4096];      // 32 KB transpose buffer
    __shared__ ull Gp[64];                     // 8 gates x 8 packed consts
    __shared__ float2 cst[NQ * TB];            // (cos,sin) per (wire,b) first pass

    int tid = threadIdx.x;
    int b = tid & 15, thi = tid >> 4;

    unsigned rep = 0;
#pragma unroll
    for (int k = 0; k < 8; k++)
        if ((blockIdx.x >> k) & 1) rep |= (1u << pa.freepos[k]);

    // per-CTA selector bits, folded into index XORs
    unsigned flA = 0, flB = 0;
#pragma unroll
    for (int g = 0; g < 4; g++) {
        flA |= (unsigned)(__popc((unsigned)pa.selrow[g] & rep) & 1) << g;
        flB |= (unsigned)(__popc((unsigned)pa.selrow[4 + g] & rep) & 1) << g;
    }

    // gate matrices (CTA-uniform, standard orientation), packed:
    // per coefficient u: A=(u.re,u.re), B=(-u.im,u.im)
    if (tid < 8) {
        const float* wp = wts + ((size_t)pa.layer * NQ + pa.gbase + tid) * 3;
        float phi = wp[0], th = wp[1], om = wp[2];
        float c, s, ca, sa, cb, sb;
        sincosf(0.5f * th, &s, &c);
        sincosf(0.5f * (phi + om), &sa, &ca);
        sincosf(0.5f * (phi - om), &sb, &cb);
        ull* g = Gp + tid * 8;
        // u00=(c*ca,-c*sa) u01=(-s*cb,-s*sb) u10=(s*cb,-s*sb) u11=(c*ca,c*sa)
        g[0] = pack2(c * ca, c * ca);   g[1] = pack2(c * sa, -c * sa);
        g[2] = pack2(-s * cb, -s * cb); g[3] = pack2(s * sb, -s * sb);
        g[4] = pack2(s * cb, s * cb);   g[5] = pack2(s * sb, -s * sb);
        g[6] = pack2(c * ca, c * ca);   g[7] = pack2(-c * sa, c * sa);
    }
    if (pa.first) {
        int wi = tid >> 4, bb2 = tid & 15;
        float s, c;
        sincospif(0.5f * x[(pa.b0 + blockIdx.y * TB + bb2) * NQ + wi], &s, &c);
        cst[wi * TB + bb2] = make_float2(c, s);
    }
    __syncthreads();

    int bbase = pa.b0 + blockIdx.y * TB;
    size_t off = (size_t)bbase + b;

    // ---- Round A: gates 0-3. v[jj] holds slot t=thi*16+(jj^flA). -----------
    unsigned p[16];
    {
        unsigned baseA = rep ^ mx4(pa.mask + 4, (unsigned)thi) ^ mx4(pa.mask, flA);
        xtree(p, baseA, pa.mask[0], pa.mask[1], pa.mask[2], pa.mask[3]);
    }
    ull v[16];
    if (!pa.first) {
#pragma unroll
        for (int j = 0; j < 16; j++)
            v[j] = g_state[(size_t)p[j] * BATCH + off];
    } else {
#pragma unroll
        for (int j = 0; j < 16; j++) {
            float a = 1.0f;
#pragma unroll
            for (int i = 0; i < NQ; i++) {
                float2 c = cst[i * TB + b];
                a *= ((p[j] >> i) & 1) ? c.y : c.x;
            }
            v[j] = pack2(a, 0.0f);
        }
    }
    bfly4(v, Gp, 0);
#pragma unroll
    for (int j = 0; j < 16; j++) S[thi * 256 + j * 16 + b] = v[j];
    __syncthreads();

    // ---- Round B: gates 4-7. v[kk] holds slot t=(kk^flB)*16+thi. -----------
    {
        int c0 = ((thi ^ (int)flA) << 4) + b;
#pragma unroll
        for (int k = 0; k < 16; k++) v[k] = S[((k ^ (int)flB) << 8) + c0];
    }
    bfly4(v, Gp, 4);

    if (!pa.last) {
        unsigned baseB = rep ^ mx4(pa.mask, (unsigned)thi) ^ mx4(pa.mask + 4, flB);
        xtree(p, baseB, pa.mask[4], pa.mask[5], pa.mask[6], pa.mask[7]);
#pragma unroll
        for (int k = 0; k < 16; k++)
            g_state[(size_t)p[k] * BATCH + off] = v[k];
    } else {
        // fused measurement: sign-words are GF(2)-linear in slot index
        unsigned swbase = 0;
#pragma unroll
        for (int k = 0; k < 8; k++)
            if ((blockIdx.x >> k) & 1) swbase ^= pa.sfb[k];
        swbase ^= mx4(pa.sm0, (unsigned)thi) ^ mx4(pa.sm4, flB);
        float acc[16];
#pragma unroll
        for (int i = 0; i < 16; i++) acc[i] = 0.0f;
#pragma unroll
        for (int k = 0; k < 16; k++) {
            float2 f = unpk(v[k]);
            float w = f.x * f.x + f.y * f.y;
            unsigned sw = swbase ^ mx4(pa.sm4, (unsigned)k);
#pragma unroll
            for (int i = 0; i < 16; i++)
                acc[i] += ((sw >> i) & 1) ? -w : w;
        }
        __syncthreads();                       // all S reads done
        float* Sf = (float*)S;                 // 256*17 floats, conflict-free
#pragma unroll
        for (int i = 0; i < 16; i++) Sf[tid * 17 + i] = acc[i];
        __syncthreads();
        int bb = tid >> 4, ii = tid & 15;
        float s = 0.0f;
#pragma unroll
        for (int t = 0; t < 16; t++) s += Sf[(t * 16 + bb) * 17 + ii];
        g_part[(size_t)blockIdx.x * (BATCH * NQ) + (size_t)(bbase + bb) * NQ + ii] = s;
    }
}

// Final deterministic reduction over 256 cosets -> out[b*16+i]
__global__ __launch_bounds__(256) void qsim_final(float* __restrict__ out) {
    int v = blockIdx.x * 256 + threadIdx.x;   // 0..8191
    float s = 0.0f;
    for (int c = 0; c < 256; c++) s += g_part[(size_t)c * (BATCH * NQ) + v];
    out[v] = s;
}

// ---------------------------------------------------------------------------
extern "C" void kernel_launch(void* const* d_in, const int* in_sizes, int n_in,
                              void* d_out, int out_size) {
    const float* x = (const float*)d_in[0];
    const float* w = (const float*)d_in[1];
    float* out = (float*)d_out;

    // Host-side GF(2) tracking of the CNOT network.
    unsigned short Lrow[NQ], Licol[NQ];
    for (int i = 0; i < NQ; i++) { Lrow[i] = (unsigned short)(1u << i); Licol[i] = (unsigned short)(1u << i); }

    static PassArgs pa[NL][2];
    for (int l = 0; l < NL; l++) {
        for (int half = 0; half < 2; half++) {
            PassArgs& a = pa[l][half];
            a.layer = l; a.gbase = half * 8; a.b0 = 0; a.first = 0; a.last = 0;
            for (int k = 0; k < 8; k++) {
                a.mask[k] = Licol[half * 8 + k];
                a.selrow[k] = Lrow[half * 8 + k];
            }
            for (int k = 0; k < 4; k++) { a.sm0[k] = 0; a.sm4[k] = 0; }
            for (int k = 0; k < 8; k++) a.sfb[k] = 0;
            // RREF over the 8 masks -> pivot bits; free bits index coset reps
            unsigned short red[8]; int piv[8]; unsigned pivmask = 0;
            for (int k = 0; k < 8; k++) {
                unsigned short vv = a.mask[k];
                for (int j = 0; j < k; j++)
                    if ((vv >> piv[j]) & 1) vv ^= red[j];
                int pbit = 0;
                while (!((vv >> pbit) & 1)) pbit++;
                piv[k] = pbit; red[k] = vv; pivmask |= (1u << pbit);
                for (int j = 0; j < k; j++)
                    if ((red[j] >> pbit) & 1) red[j] ^= vv;
            }
            int f = 0;
            for (int bit = 0; bit < NQ; bit++)
                if (!((pivmask >> bit) & 1)) a.freepos[f++] = (unsigned char)bit;
        }
        int r = l % (NQ - 1) + 1;
        for (int i = 0; i < NQ; i++) {
            int c = i, t = (i + r) % NQ;
            Lrow[t] = (unsigned short)(Lrow[t] ^ Lrow[c]);
            Licol[c] = (unsigned short)(Licol[c] ^ Licol[t]);
        }
    }
    // sign-words for the fused measurement (final Lrow, last pass's masks)
    {
        PassArgs& lp = pa[NL - 1][1];
        auto sw16 = [&](unsigned m) -> unsigned short {
            unsigned r = 0;
            for (int i = 0; i < NQ; i++) {
                unsigned v = (unsigned)Lrow[i] & m;
                v ^= v >> 8; v ^= v >> 4; v ^= v >> 2; v ^= v >> 1;
                r |= (v & 1u) << i;
            }
            return (unsigned short)r;
        };
        for (int g = 0; g < 4; g++) {
            lp.sm0[g] = sw16(lp.mask[g]);
            lp.sm4[g] = sw16(lp.mask[4 + g]);
        }
        for (int k = 0; k < 8; k++) lp.sfb[k] = sw16(1u << lp.freepos[k]);
    }

    for (int c = 0; c < NCHUNK; c++) {
        int b0 = c * BCHUNK;
        for (int l = 0; l < NL; l++)
            for (int half = 0; half < 2; half++) {
                PassArgs a = pa[l][half];
                a.b0 = b0;
                a.first = (l == 0 && half == 0) ? 1 : 0;
                a.last = (l == NL - 1 && half == 1) ? 1 : 0;
                qsim_pass<<<dim3(256, NBT), 256>>>(x, w, a);
            }
    }
    qsim_final<<<32, 256>>>(out);
}

// round 6
// speedup vs baseline: 2.1462x; 1.1577x over previous
#include <cuda_runtime.h>
#include <cstdint>

#define NQ 16
#define NL 8
#define BATCH 512
#define DIM 65536
#define BCHUNK 128
#define NCHUNK (BATCH / BCHUNK)
#define TB 16
#define NBT (BCHUNK / TB)

typedef unsigned long long ull;

// 256 MB state, packed complex (lo=re, hi=im), layout [slot][batch]
__device__ ull g_state[(size_t)DIM * BATCH];
// measurement partials [coset 0..255][batch][wire]
__device__ float g_part[(size_t)256 * BATCH * NQ];

struct PassArgs {
    unsigned short xcA[16];     // XOR-combos of masks 0-3 (linear in index)
    unsigned short xcB[16];     // XOR-combos of masks 4-7
    unsigned short selrow[8];   // Lrow of the 8 wires (selector rows)
    unsigned char  freepos[8];  // coset representative bit positions
    unsigned short smA[16];     // sign-words of xcA (last pass)
    unsigned short smB[16];     // sign-words of xcB (last pass)
    unsigned short sfb[8];      // sign-words of freepos bits (last pass)
    int layer, gbase, b0, first, last;
};

// ---- packed f32x2 helpers (Blackwell) -------------------------------------
__device__ __forceinline__ ull ffma2(ull a, ull b, ull c) {
    ull d;
    asm("fma.rn.f32x2 %0, %1, %2, %3;" : "=l"(d) : "l"(a), "l"(b), "l"(c));
    return d;
}
__device__ __forceinline__ ull fmul2(ull a, ull b) {
    ull d;
    asm("mul.rn.f32x2 %0, %1, %2;" : "=l"(d) : "l"(a), "l"(b));
    return d;
}
__device__ __forceinline__ ull swap2(ull a) {
    ull d;
    asm("{\n\t.reg .b32 lo, hi;\n\tmov.b64 {lo, hi}, %1;\n\tmov.b64 %0, {hi, lo};\n\t}"
        : "=l"(d) : "l"(a));
    return d;
}
__device__ __forceinline__ ull pack2(float lo, float hi) {
    ull d;
    asm("mov.b64 %0, {%1, %2};" : "=l"(d) : "f"(lo), "f"(hi));
    return d;
}
__device__ __forceinline__ float2 unpk(ull a) {
    float2 f;
    asm("mov.b64 {%0, %1}, %2;" : "=f"(f.x), "=f"(f.y) : "l"(a));
    return f;
}

__device__ __forceinline__ void bfly4(ull* v, const ull* Gp, int gofs) {
#pragma unroll
    for (int g = 0; g < 4; g++) {
        ull gc[8];
#pragma unroll
        for (int k = 0; k < 8; k++) gc[k] = Gp[(gofs + g) * 8 + k];
#pragma unroll
        for (int j = 0; j < 16; j++) {
            if (j & (1 << g)) continue;
            int j1 = j | (1 << g);
            ull a0 = v[j], a1 = v[j1];
            ull a0s = swap2(a0), a1s = swap2(a1);
            v[j]  = ffma2(gc[0], a0, ffma2(gc[1], a0s, ffma2(gc[2], a1, fmul2(gc[3], a1s))));
            v[j1] = ffma2(gc[4], a0, ffma2(gc[5], a0s, ffma2(gc[6], a1, fmul2(gc[7], a1s))));
        }
    }
}

// ---------------------------------------------------------------------------
// Pass: 8 Rot gates (half a layer) on a 256-coset x 16-batch tile.
// grid (256 cosets, NBT), 256 threads. first: synthesize product state.
// last: fuse <Z_i> measurement, skip state writeback.
// ---------------------------------------------------------------------------
__global__ __launch_bounds__(256, 4) void qsim_pass(const float* __restrict__ x,
                                                    const float* __restrict__ wts,
                                                    const PassArgs pa) {
    __shared__ __align__(16) ull S[4096];      // 32 KB transpose buffer
    __shared__ ull Gp[64];                     // 8 gates x 8 packed consts
    __shared__ float2 cst[NQ * TB];            // (cos,sin) per (wire,b) first pass

    int tid = threadIdx.x;
    int b = tid & 15, thi = tid >> 4;

    unsigned rep = 0;
#pragma unroll
    for (int k = 0; k < 8; k++)
        if ((blockIdx.x >> k) & 1) rep |= (1u << pa.freepos[k]);

    // per-CTA selector bits, folded into index XORs
    unsigned flA = 0, flB = 0;
#pragma unroll
    for (int g = 0; g < 4; g++) {
        flA |= (unsigned)(__popc((unsigned)pa.selrow[g] & rep) & 1) << g;
        flB |= (unsigned)(__popc((unsigned)pa.selrow[4 + g] & rep) & 1) << g;
    }

    int bbase = pa.b0 + blockIdx.y * TB;
    size_t off = (size_t)bbase + b;
    // v[jj] holds slot t = thi*16 + (jj^flA); p = baseA ^ xcA[jj]
    unsigned baseA = rep ^ (unsigned)pa.xcB[thi] ^ (unsigned)pa.xcA[flA];

    // issue all 16 loads FIRST (overlap gate setup + barrier with latency)
    ull v[16];
    if (!pa.first) {
#pragma unroll
        for (int j = 0; j < 16; j++)
            v[j] = g_state[(size_t)(baseA ^ (unsigned)pa.xcA[j]) * BATCH + off];
    }

    // gate matrices (CTA-uniform, standard orientation), packed:
    // per coefficient u: A=(u.re,u.re), B=(-u.im,u.im)
    if (tid < 8) {
        const float* wp = wts + ((size_t)pa.layer * NQ + pa.gbase + tid) * 3;
        float phi = wp[0], th = wp[1], om = wp[2];
        float c, s, ca, sa, cb, sb;
        sincosf(0.5f * th, &s, &c);
        sincosf(0.5f * (phi + om), &sa, &ca);
        sincosf(0.5f * (phi - om), &sb, &cb);
        ull* g = Gp + tid * 8;
        // u00=(c*ca,-c*sa) u01=(-s*cb,-s*sb) u10=(s*cb,-s*sb) u11=(c*ca,c*sa)
        g[0] = pack2(c * ca, c * ca);   g[1] = pack2(c * sa, -c * sa);
        g[2] = pack2(-s * cb, -s * cb); g[3] = pack2(s * sb, -s * sb);
        g[4] = pack2(s * cb, s * cb);   g[5] = pack2(s * sb, -s * sb);
        g[6] = pack2(c * ca, c * ca);   g[7] = pack2(-c * sa, c * sa);
    }
    if (pa.first) {
        int wi = tid >> 4, bb2 = tid & 15;
        float s, c;
        sincospif(0.5f * x[(pa.b0 + blockIdx.y * TB + bb2) * NQ + wi], &s, &c);
        cst[wi * TB + bb2] = make_float2(c, s);
    }
    __syncthreads();

    if (pa.first) {
        // synthesize product state: amp(p,b) = prod_i (bit_i(p) ? sin : cos)
#pragma unroll
        for (int j = 0; j < 16; j++) {
            unsigned p = baseA ^ (unsigned)pa.xcA[j];
            float a = 1.0f;
#pragma unroll
            for (int i = 0; i < NQ; i++) {
                float2 c = cst[i * TB + b];
                a *= ((p >> i) & 1) ? c.y : c.x;
            }
            v[j] = pack2(a, 0.0f);
        }
    }

    // ---- Round A: gates 0-3 -------------------------------------------------
    bfly4(v, Gp, 0);
#pragma unroll
    for (int j = 0; j < 16; j++) S[thi * 256 + j * 16 + b] = v[j];
    __syncthreads();

    // ---- Round B: gates 4-7. v[kk] holds slot t=(kk^flB)*16+thi. -----------
    {
        int c0 = ((thi ^ (int)flA) << 4) + b;
#pragma unroll
        for (int k = 0; k < 16; k++) v[k] = S[((k ^ (int)flB) << 8) + c0];
    }
    bfly4(v, Gp, 4);

    if (!pa.last) {
        unsigned baseB = rep ^ (unsigned)pa.xcA[thi] ^ (unsigned)pa.xcB[flB];
#pragma unroll
        for (int k = 0; k < 16; k++)
            g_state[(size_t)(baseB ^ (unsigned)pa.xcB[k]) * BATCH + off] = v[k];
    } else {
        // fused measurement: sign-words are GF(2)-linear in slot index
        unsigned swbase = 0;
#pragma unroll
        for (int k = 0; k < 8; k++)
            if ((blockIdx.x >> k) & 1) swbase ^= pa.sfb[k];
        swbase ^= (unsigned)pa.smA[thi] ^ (unsigned)pa.smB[flB];
        float acc[16];
#pragma unroll
        for (int i = 0; i < 16; i++) acc[i] = 0.0f;
#pragma unroll
        for (int k = 0; k < 16; k++) {
            float2 f = unpk(v[k]);
            float w = f.x * f.x + f.y * f.y;
            unsigned sw = swbase ^ (unsigned)pa.smB[k];
#pragma unroll
            for (int i = 0; i < 16; i++)
                acc[i] += ((sw >> i) & 1) ? -w : w;
        }
        __syncthreads();                       // all S reads done
        float* Sf = (float*)S;                 // 256*17 floats, conflict-free
#pragma unroll
        for (int i = 0; i < 16; i++) Sf[tid * 17 + i] = acc[i];
        __syncthreads();
        int bb = tid >> 4, ii = tid & 15;
        float s = 0.0f;
#pragma unroll
        for (int t = 0; t < 16; t++) s += Sf[(t * 16 + bb) * 17 + ii];
        g_part[(size_t)blockIdx.x * (BATCH * NQ) + (size_t)(bbase + bb) * NQ + ii] = s;
    }
}

// Final deterministic reduction over 256 cosets -> out[b*16+i]
__global__ __launch_bounds__(256) void qsim_final(float* __restrict__ out) {
    int v = blockIdx.x * 256 + threadIdx.x;   // 0..8191
    float s = 0.0f;
    for (int c = 0; c < 256; c++) s += g_part[(size_t)c * (BATCH * NQ) + v];
    out[v] = s;
}

// ---------------------------------------------------------------------------
extern "C" void kernel_launch(void* const* d_in, const int* in_sizes, int n_in,
                              void* d_out, int out_size) {
    const float* x = (const float*)d_in[0];
    const float* w = (const float*)d_in[1];
    float* out = (float*)d_out;

    // Host-side GF(2) tracking of the CNOT network.
    unsigned short Lrow[NQ], Licol[NQ];
    for (int i = 0; i < NQ; i++) { Lrow[i] = (unsigned short)(1u << i); Licol[i] = (unsigned short)(1u << i); }

    static PassArgs pa[NL][2];
    for (int l = 0; l < NL; l++) {
        for (int half = 0; half < 2; half++) {
            PassArgs& a = pa[l][half];
            a.layer = l; a.gbase = half * 8; a.b0 = 0; a.first = 0; a.last = 0;
            unsigned short mask[8];
            for (int k = 0; k < 8; k++) {
                mask[k] = Licol[half * 8 + k];
                a.selrow[k] = Lrow[half * 8 + k];
            }
            // XOR-combination tables (GF(2)-linear in index)
            for (int j = 0; j < 16; j++) {
                unsigned vA = 0, vB = 0;
                for (int bit = 0; bit < 4; bit++)
                    if ((j >> bit) & 1) { vA ^= mask[bit]; vB ^= mask[4 + bit]; }
                a.xcA[j] = (unsigned short)vA;
                a.xcB[j] = (unsigned short)vB;
            }
            for (int j = 0; j < 16; j++) { a.smA[j] = 0; a.smB[j] = 0; }
            for (int k = 0; k < 8; k++) a.sfb[k] = 0;
            // RREF over the 8 masks -> pivot bits; free bits index coset reps
            unsigned short red[8]; int piv[8]; unsigned pivmask = 0;
            for (int k = 0; k < 8; k++) {
                unsigned short vv = mask[k];
                for (int j = 0; j < k; j++)
                    if ((vv >> piv[j]) & 1) vv ^= red[j];
                int pbit = 0;
                while (!((vv >> pbit) & 1)) pbit++;
                piv[k] = pbit; red[k] = vv; pivmask |= (1u << pbit);
                for (int j = 0; j < k; j++)
                    if ((red[j] >> pbit) & 1) red[j] ^= vv;
            }
            int f = 0;
            for (int bit = 0; bit < NQ; bit++)
                if (!((pivmask >> bit) & 1)) a.freepos[f++] = (unsigned char)bit;
        }
        int r = l % (NQ - 1) + 1;
        for (int i = 0; i < NQ; i++) {
            int c = i, t = (i + r) % NQ;
            Lrow[t] = (unsigned short)(Lrow[t] ^ Lrow[c]);
            Licol[c] = (unsigned short)(Licol[c] ^ Licol[t]);
        }
    }
    // sign-words for the fused measurement (final Lrow, last pass's combos)
    {
        PassArgs& lp = pa[NL - 1][1];
        auto sw16 = [&](unsigned m) -> unsigned short {
            unsigned r = 0;
            for (int i = 0; i < NQ; i++) {
                unsigned v = (unsigned)Lrow[i] & m;
                v ^= v >> 8; v ^= v >> 4; v ^= v >> 2; v ^= v >> 1;
                r |= (v & 1u) << i;
            }
            return (unsigned short)r;
        };
        for (int j = 0; j < 16; j++) {
            lp.smA[j] = sw16(lp.xcA[j]);
            lp.smB[j] = sw16(lp.xcB[j]);
        }
        for (int k = 0; k < 8; k++) lp.sfb[k] = sw16(1u << lp.freepos[k]);
    }

    for (int c = 0; c < NCHUNK; c++) {
        int b0 = c * BCHUNK;
        for (int l = 0; l < NL; l++)
            for (int half = 0; half < 2; half++) {
                PassArgs a = pa[l][half];
                a.b0 = b0;
                a.first = (l == 0 && half == 0) ? 1 : 0;
                a.last = (l == NL - 1 && half == 1) ? 1 : 0;
                qsim_pass<<<dim3(256, NBT), 256>>>(x, w, a);
            }
    }
    qsim_final<<<32, 256>>>(out);
}

// round 7
// speedup vs baseline: 2.6497x; 1.2346x over previous
#include <cuda_runtime.h>
#include <cstdint>

#define NQ 16
#define NL 8
#define BATCH 512
#define DIM 65536
#define BCHUNK 128
#define NCHUNK (BATCH / BCHUNK)
#define TB 16
#define NBT (BCHUNK / TB)

typedef unsigned long long ull;

// 256 MB state, packed complex (lo=re, hi=im), layout [slot][batch]
__device__ ull g_state[(size_t)DIM * BATCH];
// measurement partials [coset 0..255][batch][wire]
__device__ float g_part[(size_t)256 * BATCH * NQ];

struct PassArgs {
    unsigned short xcA[16];     // XOR-combos of masks 0-3 (linear in index)
    unsigned short xcB[16];     // XOR-combos of masks 4-7
    unsigned short selrow[8];   // Lrow of the 8 wires (selector rows)
    unsigned char  freepos[8];  // coset representative bit positions
    unsigned short smA[16];     // sign-words of xcA (last pass)
    unsigned short smB[16];     // sign-words of xcB (last pass)
    unsigned short sfb[8];      // sign-words of freepos bits (last pass)
    unsigned int   WxcA[16];    // diag parity-words of xcA (pass A)
    unsigned int   WxcB[16];    // diag parity-words of xcB (pass A)
    unsigned int   Wfb[8];      // diag parity-words of rep bits (pass A)
    int layer, gbase, b0, first, last, hasdiag;
};

// ---- packed f32x2 helpers (Blackwell) -------------------------------------
__device__ __forceinline__ ull ffma2(ull a, ull b, ull c) {
    ull d;
    asm("fma.rn.f32x2 %0, %1, %2, %3;" : "=l"(d) : "l"(a), "l"(b), "l"(c));
    return d;
}
__device__ __forceinline__ ull fmul2(ull a, ull b) {
    ull d;
    asm("mul.rn.f32x2 %0, %1, %2;" : "=l"(d) : "l"(a), "l"(b));
    return d;
}
__device__ __forceinline__ ull swap2(ull a) {
    ull d;
    asm("{\n\t.reg .b32 lo, hi;\n\tmov.b64 {lo, hi}, %1;\n\tmov.b64 %0, {hi, lo};\n\t}"
        : "=l"(d) : "l"(a));
    return d;
}
__device__ __forceinline__ ull pack2(float lo, float hi) {
    ull d;
    asm("mov.b64 %0, {%1, %2};" : "=l"(d) : "f"(lo), "f"(hi));
    return d;
}
__device__ __forceinline__ float2 unpk(ull a) {
    float2 f;
    asm("mov.b64 {%0, %1}, %2;" : "=f"(f.x), "=f"(f.y) : "l"(a));
    return f;
}

// real RY butterflies: r0 = c*a0 - s*a1, r1 = s*a0 + c*a1 (componentwise)
__device__ __forceinline__ void bfly4_ry(ull* v, const ull* Gp, int gofs) {
#pragma unroll
    for (int g = 0; g < 4; g++) {
        ull C = Gp[(gofs + g) * 3 + 0];
        ull Sp = Gp[(gofs + g) * 3 + 1];
        ull Sn = Gp[(gofs + g) * 3 + 2];
#pragma unroll
        for (int j = 0; j < 16; j++) {
            if (j & (1 << g)) continue;
            int j1 = j | (1 << g);
            ull a0 = v[j], a1 = v[j1];
            v[j]  = ffma2(C, a0, fmul2(Sn, a1));
            v[j1] = ffma2(Sp, a0, fmul2(C, a1));
        }
    }
}

// ---------------------------------------------------------------------------
// Pass: 8 RY gates (half a layer) on a 256-coset x 16-batch tile.
// hasdiag (pass A only): apply merged RZ diagonal (omega_{l-1} + phi_l) first.
// first: synthesize product state. last: fuse <Z_i> measurement.
// ---------------------------------------------------------------------------
__global__ __launch_bounds__(256, 4) void qsim_pass(const float* __restrict__ x,
                                                    const float* __restrict__ wts,
                                                    const PassArgs pa) {
    __shared__ __align__(16) ull S[4096];      // 32 KB transpose buffer
    __shared__ ull Gp[24];                     // 8 gates x {C, S, -S} packed
    __shared__ ulonglong2 Ph[256];             // diag phase table (pass A)
    __shared__ float2 cst[NQ * TB];            // (cos,sin) per (wire,b) first pass

    int tid = threadIdx.x;
    int b = tid & 15, thi = tid >> 4;

    unsigned rep = 0;
#pragma unroll
    for (int k = 0; k < 8; k++)
        if ((blockIdx.x >> k) & 1) rep |= (1u << pa.freepos[k]);

    // per-CTA selector bits, folded into index XORs
    unsigned flA = 0, flB = 0;
#pragma unroll
    for (int g = 0; g < 4; g++) {
        flA |= (unsigned)(__popc((unsigned)pa.selrow[g] & rep) & 1) << g;
        flB |= (unsigned)(__popc((unsigned)pa.selrow[4 + g] & rep) & 1) << g;
    }

    int bbase = pa.b0 + blockIdx.y * TB;
    size_t off = (size_t)bbase + b;
    // v[jj] holds slot t = thi*16 + (jj^flA); p = baseA ^ xcA[jj]
    unsigned baseA = rep ^ (unsigned)pa.xcB[thi] ^ (unsigned)pa.xcA[flA];

    // issue all 16 loads FIRST (overlap setup + barrier with latency)
    ull v[16];
    if (!pa.first) {
#pragma unroll
        for (int j = 0; j < 16; j++)
            v[j] = g_state[(size_t)(baseA ^ (unsigned)pa.xcA[j]) * BATCH + off];
    }

    // RY gate constants (CTA-uniform; selector flips folded into index XOR)
    if (tid < 8) {
        float th = wts[((size_t)pa.layer * NQ + pa.gbase + tid) * 3 + 1];
        float c, s;
        sincosf(0.5f * th, &s, &c);
        Gp[tid * 3 + 0] = pack2(c, c);
        Gp[tid * 3 + 1] = pack2(s, s);
        Gp[tid * 3 + 2] = pack2(-s, -s);
    }
    // diag phase table: one slot per thread, 32 GF(2)-parity-selected terms
    if (pa.hasdiag) {
        unsigned Wr = 0;
#pragma unroll
        for (int k = 0; k < 8; k++)
            if ((blockIdx.x >> k) & 1) Wr ^= pa.Wfb[k];
        unsigned W = Wr ^ pa.WxcB[tid >> 4] ^ pa.WxcA[tid & 15];
        int l2 = pa.layer > 0 ? pa.layer - 1 : 0;
        float phv = 0.0f;
#pragma unroll
        for (int k = 0; k < 16; k++)
            phv += ((W >> k) & 1) ? __ldg(&wts[((size_t)pa.layer * NQ + k) * 3 + 0]) : 0.0f;
#pragma unroll
        for (int k = 0; k < 16; k++)
            phv += ((W >> (16 + k)) & 1) ? __ldg(&wts[((size_t)l2 * NQ + k) * 3 + 2]) : 0.0f;
        float sp, cp;
        sincosf(phv, &sp, &cp);
        Ph[tid] = make_ulonglong2(pack2(cp, cp), pack2(-sp, sp));
    }
    if (pa.first) {
        int wi = tid >> 4, bb2 = tid & 15;
        float s, c;
        sincospif(0.5f * x[(pa.b0 + blockIdx.y * TB + bb2) * NQ + wi], &s, &c);
        cst[wi * TB + bb2] = make_float2(c, s);
    }
    __syncthreads();

    if (pa.first) {
        // synthesize product state: amp(p,b) = prod_i (bit_i(p) ? sin : cos)
#pragma unroll
        for (int j = 0; j < 16; j++) {
            unsigned p = baseA ^ (unsigned)pa.xcA[j];
            float a = 1.0f;
#pragma unroll
            for (int i = 0; i < NQ; i++) {
                float2 c = cst[i * TB + b];
                a *= ((p >> i) & 1) ? c.y : c.x;
            }
            v[j] = pack2(a, 0.0f);
        }
    }

    // apply merged RZ diagonal (phase per slot, shared across batches)
    if (pa.hasdiag) {
#pragma unroll
        for (int j = 0; j < 16; j++) {
            ulonglong2 ph = Ph[thi * 16 + (j ^ (int)flA)];
            v[j] = ffma2(ph.x, v[j], fmul2(ph.y, swap2(v[j])));
        }
    }

    // ---- Round A: gates 0-3 -------------------------------------------------
    bfly4_ry(v, Gp, 0);
#pragma unroll
    for (int j = 0; j < 16; j++) S[thi * 256 + j * 16 + b] = v[j];
    __syncthreads();

    // ---- Round B: gates 4-7. v[kk] holds slot t=(kk^flB)*16+thi. -----------
    {
        int c0 = ((thi ^ (int)flA) << 4) + b;
#pragma unroll
        for (int k = 0; k < 16; k++) v[k] = S[((k ^ (int)flB) << 8) + c0];
    }
    bfly4_ry(v, Gp, 4);

    if (!pa.last) {
        unsigned baseB = rep ^ (unsigned)pa.xcA[thi] ^ (unsigned)pa.xcB[flB];
#pragma unroll
        for (int k = 0; k < 16; k++)
            g_state[(size_t)(baseB ^ (unsigned)pa.xcB[k]) * BATCH + off] = v[k];
    } else {
        // fused measurement: sign-words are GF(2)-linear in slot index
        unsigned swbase = 0;
#pragma unroll
        for (int k = 0; k < 8; k++)
            if ((blockIdx.x >> k) & 1) swbase ^= pa.sfb[k];
        swbase ^= (unsigned)pa.smA[thi] ^ (unsigned)pa.smB[flB];
        float acc[16];
#pragma unroll
        for (int i = 0; i < 16; i++) acc[i] = 0.0f;
#pragma unroll
        for (int k = 0; k < 16; k++) {
            float2 f = unpk(v[k]);
            float w = f.x * f.x + f.y * f.y;
            unsigned sw = swbase ^ (unsigned)pa.smB[k];
#pragma unroll
            for (int i = 0; i < 16; i++)
                acc[i] += ((sw >> i) & 1) ? -w : w;
        }
        __syncthreads();                       // all S reads done
        float* Sf = (float*)S;                 // 256*17 floats, conflict-free
#pragma unroll
        for (int i = 0; i < 16; i++) Sf[tid * 17 + i] = acc[i];
        __syncthreads();
        int bb = tid >> 4, ii = tid & 15;
        float s = 0.0f;
#pragma unroll
        for (int t = 0; t < 16; t++) s += Sf[(t * 16 + bb) * 17 + ii];
        g_part[(size_t)blockIdx.x * (BATCH * NQ) + (size_t)(bbase + bb) * NQ + ii] = s;
    }
}

// Final deterministic reduction over 256 cosets -> out[b*16+i]
__global__ __launch_bounds__(256) void qsim_final(float* __restrict__ out) {
    int v = blockIdx.x * 256 + threadIdx.x;   // 0..8191
    float s = 0.0f;
    for (int c = 0; c < 256; c++) s += g_part[(size_t)c * (BATCH * NQ) + v];
    out[v] = s;
}

// ---------------------------------------------------------------------------
static unsigned par16(unsigned v) {
    v ^= v >> 8; v ^= v >> 4; v ^= v >> 2; v ^= v >> 1;
    return v & 1u;
}

extern "C" void kernel_launch(void* const* d_in, const int* in_sizes, int n_in,
                              void* d_out, int out_size) {
    const float* x = (const float*)d_in[0];
    const float* w = (const float*)d_in[1];
    float* out = (float*)d_out;

    // Host-side GF(2) tracking of the CNOT network.
    unsigned short Lrow[NQ], Licol[NQ];
    unsigned short LrowHist[NL][NQ];
    for (int i = 0; i < NQ; i++) { Lrow[i] = (unsigned short)(1u << i); Licol[i] = (unsigned short)(1u << i); }

    static PassArgs pa[NL][2];
    for (int l = 0; l < NL; l++) {
        for (int i = 0; i < NQ; i++) LrowHist[l][i] = Lrow[i];
        for (int half = 0; half < 2; half++) {
            PassArgs& a = pa[l][half];
            a.layer = l; a.gbase = half * 8; a.b0 = 0;
            a.first = 0; a.last = 0; a.hasdiag = (half == 0) ? 1 : 0;
            unsigned short mask[8];
            for (int k = 0; k < 8; k++) {
                mask[k] = Licol[half * 8 + k];
                a.selrow[k] = Lrow[half * 8 + k];
            }
            // XOR-combination tables (GF(2)-linear in index)
            for (int j = 0; j < 16; j++) {
                unsigned vA = 0, vB = 0;
                for (int bit = 0; bit < 4; bit++)
                    if ((j >> bit) & 1) { vA ^= mask[bit]; vB ^= mask[4 + bit]; }
                a.xcA[j] = (unsigned short)vA;
                a.xcB[j] = (unsigned short)vB;
            }
            for (int j = 0; j < 16; j++) { a.smA[j] = 0; a.smB[j] = 0; a.WxcA[j] = 0; a.WxcB[j] = 0; }
            for (int k = 0; k < 8; k++) { a.sfb[k] = 0; a.Wfb[k] = 0; }
            // RREF over the 8 masks -> pivot bits; free bits index coset reps
            unsigned short red[8]; int piv[8]; unsigned pivmask = 0;
            for (int k = 0; k < 8; k++) {
                unsigned short vv = mask[k];
                for (int j = 0; j < k; j++)
                    if ((vv >> piv[j]) & 1) vv ^= red[j];
                int pbit = 0;
                while (!((vv >> pbit) & 1)) pbit++;
                piv[k] = pbit; red[k] = vv; pivmask |= (1u << pbit);
                for (int j = 0; j < k; j++)
                    if ((red[j] >> pbit) & 1) red[j] ^= vv;
            }
            int f = 0;
            for (int bit = 0; bit < NQ; bit++)
                if (!((pivmask >> bit) & 1)) a.freepos[f++] = (unsigned char)bit;
        }
        // diag parity-word tables for pass A of layer l:
        // terms k=0..15: phi_l rows (Lrow now); k=16..31: omega_{l-1} rows (hist), 0 for l=0
        {
            PassArgs& a = pa[l][0];
            unsigned rterm[32];
            for (int k = 0; k < 16; k++) rterm[k] = LrowHist[l][k];
            for (int k = 0; k < 16; k++) rterm[16 + k] = (l > 0) ? (unsigned)LrowHist[l - 1][k] : 0u;
            for (int j = 0; j < 16; j++) {
                unsigned wA = 0, wB = 0;
                for (int k = 0; k < 32; k++) {
                    wA |= par16(rterm[k] & a.xcA[j]) << k;
                    wB |= par16(rterm[k] & a.xcB[j]) << k;
                }
                a.WxcA[j] = wA; a.WxcB[j] = wB;
            }
            for (int kk = 0; kk < 8; kk++) {
                unsigned wf = 0;
                for (int k = 0; k < 32; k++)
                    wf |= par16(rterm[k] & (1u << a.freepos[kk])) << k;
                a.Wfb[kk] = wf;
            }
        }
        int r = l % (NQ - 1) + 1;
        for (int i = 0; i < NQ; i++) {
            int c = i, t = (i + r) % NQ;
            Lrow[t] = (unsigned short)(Lrow[t] ^ Lrow[c]);
            Licol[c] = (unsigned short)(Licol[c] ^ Licol[t]);
        }
    }
    // sign-words for the fused measurement (final Lrow, last pass's combos)
    {
        PassArgs& lp = pa[NL - 1][1];
        for (int j = 0; j < 16; j++) {
            unsigned sa = 0, sb = 0;
            for (int i = 0; i < NQ; i++) {
                sa |= par16((unsigned)Lrow[i] & lp.xcA[j]) << i;
                sb |= par16((unsigned)Lrow[i] & lp.xcB[j]) << i;
            }
            lp.smA[j] = (unsigned short)sa;
            lp.smB[j] = (unsigned short)sb;
        }
        for (int k = 0; k < 8; k++) {
            unsigned sf = 0;
            for (int i = 0; i < NQ; i++)
                sf |= par16((unsigned)Lrow[i] & (1u << lp.freepos[k])) << i;
            lp.sfb[k] = (unsigned short)sf;
        }
    }

    for (int c = 0; c < NCHUNK; c++) {
        int b0 = c * BCHUNK;
        for (int l = 0; l < NL; l++)
            for (int half = 0; half < 2; half++) {
                PassArgs a = pa[l][half];
                a.b0 = b0;
                a.first = (l == 0 && half == 0) ? 1 : 0;
                a.last = (l == NL - 1 && half == 1) ? 1 : 0;
                qsim_pass<<<dim3(256, NBT), 256>>>(x, w, a);
            }
    }
    qsim_final<<<32, 256>>>(out);
}